// round 14
// baseline (speedup 1.0000x reference)
#include <cuda_runtime.h>
#include <math.h>
#include <stdint.h>

#define Dm   768
#define Hh   12
#define HDm  64
#define DFFm 3072
#define Bb   2
#define Ss   4096
#define NT   (Bb*Ss)
#define DQKV (3*Dm)   // 2304

// ---- scratch ----
__device__ float g_h   [NT*Dm];
__device__ float g_qkv [NT*DQKV];
__device__ float g_ctx [NT*Dm];
__device__ float g_x1  [NT*Dm];
__device__ float g_h2  [NT*Dm];
__device__ float g_ff1 [NT*DFFm];
__device__ float g_w   [Dm*DQKV + Dm*Dm + 2*Dm*DFFm];
__device__ float g_bqkv[DQKV];

// ---------- helpers ----------
__device__ __forceinline__ uint32_t f2tf32(float f) {
    uint32_t r;
    asm("cvt.rna.tf32.f32 %0, %1;" : "=r"(r) : "f"(f));
    return r;
}
__device__ __forceinline__ float rtf(float f) { return __uint_as_float(f2tf32(f)); }

__device__ __forceinline__ void cp_async16(void* smem, const void* gmem) {
    uint32_t s = (uint32_t)__cvta_generic_to_shared(smem);
    asm volatile("cp.async.cg.shared.global [%0], [%1], 16;" :: "r"(s), "l"(gmem));
}

__device__ __forceinline__ void ldsm_x4(uint32_t& r0, uint32_t& r1, uint32_t& r2, uint32_t& r3, uint32_t addr) {
    asm volatile("ldmatrix.sync.aligned.m8n8.x4.shared.b16 {%0,%1,%2,%3}, [%4];"
        : "=r"(r0), "=r"(r1), "=r"(r2), "=r"(r3) : "r"(addr));
}

// ============================ fused rounding pre-pass ============================
#define WQKV4 (Dm * DQKV / 4)
#define WO4   (Dm * Dm / 4)
#define WF4   (Dm * DFFm / 4)
#define TOT4  (WQKV4 + WO4 + 2 * WF4 + DQKV / 4)

__global__ void round_all_kernel(const float* __restrict__ Wq, const float* __restrict__ Wk,
                                 const float* __restrict__ Wv, const float* __restrict__ Wo,
                                 const float* __restrict__ W1, const float* __restrict__ W2,
                                 const float* __restrict__ bq, const float* __restrict__ bk,
                                 const float* __restrict__ bv,
                                 float* __restrict__ wdst, float* __restrict__ bdst) {
    const int SRC4 = Dm / 4;
    const int DST4 = DQKV / 4;
    for (int i = blockIdx.x * blockDim.x + threadIdx.x; i < TOT4; i += gridDim.x * blockDim.x) {
        float4 v; float4* dp;
        if (i < WQKV4) {
            int r = i / DST4, c = i % DST4;
            const float* src = (c < SRC4) ? Wq : (c < 2 * SRC4) ? Wk : Wv;
            int cl = (c >= 2 * SRC4) ? c - 2 * SRC4 : (c >= SRC4) ? c - SRC4 : c;
            v = ((const float4*)src)[r * SRC4 + cl];
            dp = (float4*)wdst + i;
        } else if (i < WQKV4 + WO4) {
            v = ((const float4*)Wo)[i - WQKV4];
            dp = (float4*)wdst + i;
        } else if (i < WQKV4 + WO4 + WF4) {
            v = ((const float4*)W1)[i - WQKV4 - WO4];
            dp = (float4*)wdst + i;
        } else if (i < WQKV4 + WO4 + 2 * WF4) {
            v = ((const float4*)W2)[i - WQKV4 - WO4 - WF4];
            dp = (float4*)wdst + i;
        } else {
            int c = i - (WQKV4 + WO4 + 2 * WF4);
            const float* src = (c < SRC4) ? bq : (c < 2 * SRC4) ? bk : bv;
            int cl = (c >= 2 * SRC4) ? c - 2 * SRC4 : (c >= SRC4) ? c - SRC4 : c;
            ((float4*)bdst)[c] = ((const float4*)src)[cl];
            continue;
        }
        v.x = rtf(v.x); v.y = rtf(v.y); v.z = rtf(v.z); v.w = rtf(v.w);
        *dp = v;
    }
}

// ============================ LayerNorm (tf32-rounded output) ============================
__global__ void ln_kernel(const float* __restrict__ x,
                          const float* __restrict__ g,
                          const float* __restrict__ b,
                          float* __restrict__ out) {
    int row = blockIdx.x;
    const float* xr = x + (size_t)row * Dm;
    int tid = threadIdx.x;
    float v0 = xr[tid], v1 = xr[tid + 256], v2 = xr[tid + 512];
    float s  = v0 + v1 + v2;
    float s2 = v0*v0 + v1*v1 + v2*v2;
    #pragma unroll
    for (int o = 16; o; o >>= 1) {
        s  += __shfl_xor_sync(0xffffffffu, s,  o);
        s2 += __shfl_xor_sync(0xffffffffu, s2, o);
    }
    __shared__ float ws[8], ws2[8];
    int w = tid >> 5, l = tid & 31;
    if (l == 0) { ws[w] = s; ws2[w] = s2; }
    __syncthreads();
    __shared__ float smu, srs;
    if (w == 0) {
        s  = (l < 8) ? ws[l]  : 0.f;
        s2 = (l < 8) ? ws2[l] : 0.f;
        #pragma unroll
        for (int o = 4; o; o >>= 1) {
            s  += __shfl_xor_sync(0xffffffffu, s,  o);
            s2 += __shfl_xor_sync(0xffffffffu, s2, o);
        }
        if (l == 0) {
            float mu  = s / Dm;
            float var = fmaxf(s2 / Dm - mu * mu, 0.f);
            smu = mu;
            srs = rsqrtf(var + 1e-5f);
        }
    }
    __syncthreads();
    float mu = smu, rs = srs;
    float* outr = out + (size_t)row * Dm;
    outr[tid]       = rtf((v0 - mu) * rs * g[tid]       + b[tid]);
    outr[tid + 256] = rtf((v1 - mu) * rs * g[tid + 256] + b[tid + 256]);
    outr[tid + 512] = rtf((v2 - mu) * rs * g[tid + 512] + b[tid + 512]);
}

// ============================ TF32 tensor-core GEMM (cp.async 2-stage, ldmatrix A) ============================
#define ASTR 36
#define BSTR 136
#define A_WORDS (128 * ASTR)
#define B_WORDS (32 * BSTR)
#define GEMM_SMEM (2 * (A_WORDS + B_WORDS) * 4)

template<bool RELU, bool RES, bool RNDC>
__global__ __launch_bounds__(256, 2)
void tf32gemm_kernel(const float* __restrict__ A,
                     const float* __restrict__ B,
                     const float* __restrict__ bias,
                     const float* __restrict__ res,
                     float* __restrict__ C,
                     int M, int N, int K) {
    extern __shared__ uint32_t sh[];
    uint32_t* AsBase = sh;
    uint32_t* BsBase = sh + 2 * A_WORDS;

    int tid  = threadIdx.x;
    int lane = tid & 31;
    int warp = tid >> 5;
    int warp_m = warp & 1;
    int warp_n = warp >> 1;
    int grp = lane >> 2;
    int thr = lane & 3;

    int row0 = blockIdx.y * 128;
    int col0 = blockIdx.x * 128;

    int arow = lane & 15;
    int acol = (lane >> 4) << 2;
    int aoff = (warp_m * 64 + arow) * ASTR + acol;

    float c[4][4][4];
    #pragma unroll
    for (int mt = 0; mt < 4; mt++)
        #pragma unroll
        for (int nt = 0; nt < 4; nt++)
            #pragma unroll
            for (int i = 0; i < 4; i++) c[mt][nt][i] = 0.f;

    auto load_tile = [&](int k0, int stg) {
        uint32_t* Ad = AsBase + stg * A_WORDS;
        uint32_t* Bd = BsBase + stg * B_WORDS;
        #pragma unroll
        for (int it = 0; it < 4; it++) {
            int i = it * 256 + tid;
            int r = i >> 3, kc = (i & 7) * 4;
            cp_async16(&Ad[r * ASTR + kc], A + (size_t)(row0 + r) * K + k0 + kc);
        }
        #pragma unroll
        for (int it = 0; it < 4; it++) {
            int i = it * 256 + tid;
            int kr = i >> 5, nc = (i & 31) * 4;
            cp_async16(&Bd[kr * BSTR + nc], B + (size_t)(k0 + kr) * N + col0 + nc);
        }
        asm volatile("cp.async.commit_group;" ::: "memory");
    };

    int NK = K >> 5;
    load_tile(0, 0);

    for (int i = 0; i < NK; i++) {
        if (i + 1 < NK) {
            load_tile((i + 1) << 5, (i + 1) & 1);
            asm volatile("cp.async.wait_group 1;" ::: "memory");
        } else {
            asm volatile("cp.async.wait_group 0;" ::: "memory");
        }
        __syncthreads();

        const uint32_t* As = AsBase + (i & 1) * A_WORDS;
        const uint32_t* Bs = BsBase + (i & 1) * B_WORDS;
        uint32_t asU = (uint32_t)__cvta_generic_to_shared(As);

        #pragma unroll
        for (int ks = 0; ks < 4; ks++) {
            int kb = ks * 8;
            uint32_t af[4][4];
            #pragma unroll
            for (int mt = 0; mt < 4; mt++) {
                uint32_t addr = asU + (uint32_t)(aoff + mt * 16 * ASTR + kb) * 4u;
                ldsm_x4(af[mt][0], af[mt][1], af[mt][2], af[mt][3], addr);
            }
            uint32_t bf[4][2];
            #pragma unroll
            for (int nt = 0; nt < 4; nt++) {
                int cc = warp_n * 32 + nt * 8 + grp;
                bf[nt][0] = Bs[(kb + thr) * BSTR + cc];
                bf[nt][1] = Bs[(kb + thr + 4) * BSTR + cc];
            }
            #pragma unroll
            for (int mt = 0; mt < 4; mt++)
                #pragma unroll
                for (int nt = 0; nt < 4; nt++) {
                    asm("mma.sync.aligned.m16n8k8.row.col.f32.tf32.tf32.f32 "
                        "{%0,%1,%2,%3}, {%4,%5,%6,%7}, {%8,%9}, {%0,%1,%2,%3};"
                        : "+f"(c[mt][nt][0]), "+f"(c[mt][nt][1]),
                          "+f"(c[mt][nt][2]), "+f"(c[mt][nt][3])
                        : "r"(af[mt][0]), "r"(af[mt][1]), "r"(af[mt][2]), "r"(af[mt][3]),
                          "r"(bf[nt][0]), "r"(bf[nt][1]));
                }
        }
        __syncthreads();
    }

    #pragma unroll
    for (int mt = 0; mt < 4; mt++) {
        int r = row0 + warp_m * 64 + mt * 16 + grp;
        #pragma unroll
        for (int nt = 0; nt < 4; nt++) {
            int cc = col0 + warp_n * 32 + nt * 8 + 2 * thr;
            float b0 = bias[cc], b1 = bias[cc + 1];
            float o0 = c[mt][nt][0] + b0, o1 = c[mt][nt][1] + b1;
            float o2 = c[mt][nt][2] + b0, o3 = c[mt][nt][3] + b1;
            if (RELU) {
                o0 = fmaxf(o0, 0.f); o1 = fmaxf(o1, 0.f);
                o2 = fmaxf(o2, 0.f); o3 = fmaxf(o3, 0.f);
            }
            if (RES) {
                const float* rp0 = res + (size_t)r * N + cc;
                const float* rp1 = res + (size_t)(r + 8) * N + cc;
                o0 += rp0[0]; o1 += rp0[1];
                o2 += rp1[0]; o3 += rp1[1];
            }
            if (RNDC) {
                o0 = rtf(o0); o1 = rtf(o1); o2 = rtf(o2); o3 = rtf(o3);
            }
            *(float2*)&C[(size_t)r * N + cc]       = make_float2(o0, o1);
            *(float2*)&C[(size_t)(r + 8) * N + cc] = make_float2(o2, o3);
        }
    }
}

// ============================ TF32 tensor-core flash attention ============================
// 256 threads = 8 warps; warp (wm, wn): rows wm*16..+15, column-half wn.
// Double-buffered K/V via cp.async (raw fp32 bits). Softmax stats combined across
// warp pairs via named barriers (id 1+wm, 64 threads).
#define ATS 68
#define KV_WORDS (64 * ATS)

__global__ __launch_bounds__(256, 2)
void attn_tc_kernel(const float* __restrict__ QKV,
                    const int*   __restrict__ am,
                    float* __restrict__ O) {
    extern __shared__ uint32_t smx[];
    uint32_t* Qs = smx;                      // [64][ATS]
    uint32_t* Ks = Qs + KV_WORDS;            // [2][64][ATS]
    uint32_t* Vs = Ks + 2 * KV_WORDS;        // [2][64][ATS]
    uint32_t* Ps = Vs + 2 * KV_WORDS;        // [64][ATS]
    float* redT = (float*)(Ps + KV_WORDS);   // [8][16]
    float* redS = redT + 128;                // [8][16]

    int tid  = threadIdx.x;
    int warp = tid >> 5;
    int lane = tid & 31;
    int wm   = warp >> 1;       // 0..3 row group
    int wn   = warp & 1;        // 0..1 column half
    int grp  = lane >> 2;
    int thr  = lane & 3;

    int qt = gridDim.x - 1 - blockIdx.x;   // heavy tiles first
    int q0 = qt * 64;
    int h  = blockIdx.y;
    int b  = blockIdx.z;
    int r0 = wm * 16;

    uint32_t qsU = (uint32_t)__cvta_generic_to_shared(Qs);
    uint32_t ksU = (uint32_t)__cvta_generic_to_shared(Ks);
    uint32_t psU = (uint32_t)__cvta_generic_to_shared(Ps);

    int aoff  = (r0 + (lane & 15)) * ATS + ((lane >> 4) << 2);
    // paired K-frag ldsm.x4: matrices (nc rows | kb), (nc rows | kb+4), (nc+1 rows | kb), (nc+1 rows | kb+4)
    int koff4 = ((lane & 7) + ((lane >> 4) << 3)) * ATS + (((lane >> 3) & 1) << 2);

    const float* Qbase = QKV + ((size_t)(b * Ss + q0)) * DQKV + h * HDm;
    const float* Kbase = QKV + ((size_t)b * Ss) * DQKV + Dm + h * HDm;
    const float* Vbase = QKV + ((size_t)b * Ss) * DQKV + 2 * Dm + h * HDm;
    const int*   amb   = am + b * Ss;

    int ktiles = qt + 1;

    auto fill_kv = [&](int kt, int stg) {
        const float* Kb = Kbase + (size_t)(kt * 64) * DQKV;
        const float* Vb = Vbase + (size_t)(kt * 64) * DQKV;
        uint32_t* Kd = Ks + stg * KV_WORDS;
        uint32_t* Vd = Vs + stg * KV_WORDS;
        #pragma unroll
        for (int it = 0; it < 4; it++) {
            int i = it * 256 + tid;
            int r = i >> 4, c = (i & 15) * 4;
            cp_async16(&Kd[r * ATS + c], Kb + (size_t)r * DQKV + c);
            cp_async16(&Vd[r * ATS + c], Vb + (size_t)r * DQKV + c);
        }
        asm volatile("cp.async.commit_group;" ::: "memory");
    };

    fill_kv(0, 0);

    // Q: scaled + RNA-rounded once per CTA
    for (int i = tid; i < 64 * 16; i += 256) {
        int r = i >> 4, c = (i & 15) * 4;
        float4 v = *(const float4*)(Qbase + (size_t)r * DQKV + c);
        uint4 t;
        t.x = f2tf32(v.x * 0.125f); t.y = f2tf32(v.y * 0.125f);
        t.z = f2tf32(v.z * 0.125f); t.w = f2tf32(v.w * 0.125f);
        *(uint4*)&Qs[r * ATS + c] = t;
    }

    float o[4][4];
    #pragma unroll
    for (int nv = 0; nv < 4; nv++)
        #pragma unroll
        for (int i = 0; i < 4; i++) o[nv][i] = 0.f;
    float m0 = -INFINITY, m1 = -INFINITY, l0 = 0.f, l1 = 0.f;

    int qg0 = q0 + r0 + grp;
    int qg1 = qg0 + 8;
    int pairIdx = wm * 2 + wn;
    int partnerIdx = wm * 2 + (wn ^ 1);

    for (int kt = 0; kt < ktiles; kt++) {
        int k0 = kt * 64;
        if (kt + 1 < ktiles) {
            fill_kv(kt + 1, (kt + 1) & 1);
            asm volatile("cp.async.wait_group 1;" ::: "memory");
        } else {
            asm volatile("cp.async.wait_group 0;" ::: "memory");
        }
        __syncthreads();

        uint32_t ksCur = ksU + (uint32_t)((kt & 1) * KV_WORDS) * 4u;
        const uint32_t* VsCur = Vs + (kt & 1) * KV_WORDS;

        // ---- S = Q K^T for own 4 nc blocks ----
        float s[4][4];
        #pragma unroll
        for (int nc = 0; nc < 4; nc++)
            #pragma unroll
            for (int i = 0; i < 4; i++) s[nc][i] = 0.f;

        #pragma unroll
        for (int ks = 0; ks < 8; ks++) {
            int kb = ks * 8;
            uint32_t a0, a1, a2, a3;
            ldsm_x4(a0, a1, a2, a3, qsU + (uint32_t)(aoff + kb) * 4u);
            #pragma unroll
            for (int p = 0; p < 2; p++) {
                int ncp = wn * 4 + p * 2;
                uint32_t b0, b1, b2, b3;
                ldsm_x4(b0, b1, b2, b3, ksCur + (uint32_t)(koff4 + ncp * 8 * ATS + kb) * 4u);
                asm("mma.sync.aligned.m16n8k8.row.col.f32.tf32.tf32.f32 "
                    "{%0,%1,%2,%3}, {%4,%5,%6,%7}, {%8,%9}, {%0,%1,%2,%3};"
                    : "+f"(s[p*2][0]), "+f"(s[p*2][1]), "+f"(s[p*2][2]), "+f"(s[p*2][3])
                    : "r"(a0), "r"(a1), "r"(a2), "r"(a3), "r"(b0), "r"(b1));
                asm("mma.sync.aligned.m16n8k8.row.col.f32.tf32.tf32.f32 "
                    "{%0,%1,%2,%3}, {%4,%5,%6,%7}, {%8,%9}, {%0,%1,%2,%3};"
                    : "+f"(s[p*2+1][0]), "+f"(s[p*2+1][1]), "+f"(s[p*2+1][2]), "+f"(s[p*2+1][3])
                    : "r"(a0), "r"(a1), "r"(a2), "r"(a3), "r"(b2), "r"(b3));
            }
        }

        // ---- mask own columns ----
        #pragma unroll
        for (int nc = 0; nc < 4; nc++) {
            int ncg = wn * 4 + nc;
            int ca = k0 + ncg * 8 + 2 * thr;
            int cb = ca + 1;
            bool va = (amb[ca] != 0), vb = (amb[cb] != 0);
            if (!(ca <= qg0 && va)) s[nc][0] = -INFINITY;
            if (!(cb <= qg0 && vb)) s[nc][1] = -INFINITY;
            if (!(ca <= qg1 && va)) s[nc][2] = -INFINITY;
            if (!(cb <= qg1 && vb)) s[nc][3] = -INFINITY;
        }

        // ---- partial row max (own half) ----
        float t0 = -INFINITY, t1 = -INFINITY;
        #pragma unroll
        for (int nc = 0; nc < 4; nc++) {
            t0 = fmaxf(t0, fmaxf(s[nc][0], s[nc][1]));
            t1 = fmaxf(t1, fmaxf(s[nc][2], s[nc][3]));
        }
        t0 = fmaxf(t0, __shfl_xor_sync(0xffffffffu, t0, 1));
        t0 = fmaxf(t0, __shfl_xor_sync(0xffffffffu, t0, 2));
        t1 = fmaxf(t1, __shfl_xor_sync(0xffffffffu, t1, 1));
        t1 = fmaxf(t1, __shfl_xor_sync(0xffffffffu, t1, 2));
        if (thr == 0) {
            redT[pairIdx * 16 + grp]     = t0;
            redT[pairIdx * 16 + grp + 8] = t1;
        }
        asm volatile("bar.sync %0, 64;" :: "r"(1 + wm) : "memory");
        t0 = fmaxf(t0, redT[partnerIdx * 16 + grp]);
        t1 = fmaxf(t1, redT[partnerIdx * 16 + grp + 8]);

        float mn0 = fmaxf(m0, t0), mn1 = fmaxf(m1, t1);
        float al0 = (mn0 == -INFINITY) ? 1.f : __expf(m0 - mn0);
        float al1 = (mn1 == -INFINITY) ? 1.f : __expf(m1 - mn1);

        // ---- exp + P store (own half) + partial sums ----
        float ps0 = 0.f, ps1 = 0.f;
        #pragma unroll
        for (int nc = 0; nc < 4; nc++) {
            int ncg = wn * 4 + nc;
            float p0 = (s[nc][0] == -INFINITY) ? 0.f : __expf(s[nc][0] - mn0);
            float p1 = (s[nc][1] == -INFINITY) ? 0.f : __expf(s[nc][1] - mn0);
            float p2 = (s[nc][2] == -INFINITY) ? 0.f : __expf(s[nc][2] - mn1);
            float p3 = (s[nc][3] == -INFINITY) ? 0.f : __expf(s[nc][3] - mn1);
            ps0 += p0 + p1;
            ps1 += p2 + p3;
            *(uint2*)&Ps[(r0 + grp) * ATS + ncg * 8 + 2 * thr]     = make_uint2(__float_as_uint(p0), __float_as_uint(p1));
            *(uint2*)&Ps[(r0 + grp + 8) * ATS + ncg * 8 + 2 * thr] = make_uint2(__float_as_uint(p2), __float_as_uint(p3));
        }
        ps0 += __shfl_xor_sync(0xffffffffu, ps0, 1);
        ps0 += __shfl_xor_sync(0xffffffffu, ps0, 2);
        ps1 += __shfl_xor_sync(0xffffffffu, ps1, 1);
        ps1 += __shfl_xor_sync(0xffffffffu, ps1, 2);
        if (thr == 0) {
            redS[pairIdx * 16 + grp]     = ps0;
            redS[pairIdx * 16 + grp + 8] = ps1;
        }
        asm volatile("bar.sync %0, 64;" :: "r"(1 + wm) : "memory");   // also publishes P halves
        ps0 += redS[partnerIdx * 16 + grp];
        ps1 += redS[partnerIdx * 16 + grp + 8];

        l0 = l0 * al0 + ps0;
        l1 = l1 * al1 + ps1;
        m0 = mn0; m1 = mn1;

        #pragma unroll
        for (int nv = 0; nv < 4; nv++) {
            o[nv][0] *= al0; o[nv][1] *= al0;
            o[nv][2] *= al1; o[nv][3] *= al1;
        }

        // ---- O += P V for own 4 head-dim blocks ----
        #pragma unroll
        for (int ks = 0; ks < 8; ks++) {
            int kb = ks * 8;
            uint32_t a0, a1, a2, a3;
            ldsm_x4(a0, a1, a2, a3, psU + (uint32_t)(aoff + kb) * 4u);
            #pragma unroll
            for (int nv = 0; nv < 4; nv++) {
                int vdg = wn * 4 + nv;
                uint32_t b0 = VsCur[(kb + thr) * ATS + vdg * 8 + grp];
                uint32_t b1 = VsCur[(kb + thr + 4) * ATS + vdg * 8 + grp];
                asm("mma.sync.aligned.m16n8k8.row.col.f32.tf32.tf32.f32 "
                    "{%0,%1,%2,%3}, {%4,%5,%6,%7}, {%8,%9}, {%0,%1,%2,%3};"
                    : "+f"(o[nv][0]), "+f"(o[nv][1]), "+f"(o[nv][2]), "+f"(o[nv][3])
                    : "r"(a0), "r"(a1), "r"(a2), "r"(a3), "r"(b0), "r"(b1));
            }
        }
        __syncthreads();   // buffer kt&1 free for prefetch; Ps/red reuse safe
    }

    float rl0 = (l0 > 0.f) ? 1.f / l0 : 0.f;
    float rl1 = (l1 > 0.f) ? 1.f / l1 : 0.f;
    float* Ob = O + ((size_t)(b * Ss + q0)) * Dm + h * HDm;
    #pragma unroll
    for (int nv = 0; nv < 4; nv++) {
        int cc = (wn * 4 + nv) * 8 + 2 * thr;
        *(float2*)(Ob + (size_t)(r0 + grp) * Dm + cc)     = make_float2(rtf(o[nv][0] * rl0), rtf(o[nv][1] * rl0));
        *(float2*)(Ob + (size_t)(r0 + grp + 8) * Dm + cc) = make_float2(rtf(o[nv][2] * rl1), rtf(o[nv][3] * rl1));
    }
}

// ============================ launch ============================
extern "C" void kernel_launch(void* const* d_in, const int* in_sizes, int n_in,
                              void* d_out, int out_size) {
    const float* x     = (const float*)d_in[0];
    const int*   am    = (const int*)  d_in[1];
    const float* ln1_g = (const float*)d_in[2];
    const float* ln1_b = (const float*)d_in[3];
    const float* ln2_g = (const float*)d_in[4];
    const float* ln2_b = (const float*)d_in[5];
    const float* Wq = (const float*)d_in[6];
    const float* bq = (const float*)d_in[7];
    const float* Wk = (const float*)d_in[8];
    const float* bk = (const float*)d_in[9];
    const float* Wv = (const float*)d_in[10];
    const float* bv = (const float*)d_in[11];
    const float* Wo = (const float*)d_in[12];
    const float* bo = (const float*)d_in[13];
    const float* W1 = (const float*)d_in[14];
    const float* b1 = (const float*)d_in[15];
    const float* W2 = (const float*)d_in[16];
    const float* b2 = (const float*)d_in[17];
    float* out = (float*)d_out;

    float *h, *qkv, *ctx, *x1, *h2, *ff1, *wbuf, *bqkv;
    cudaGetSymbolAddress((void**)&h,    g_h);
    cudaGetSymbolAddress((void**)&qkv,  g_qkv);
    cudaGetSymbolAddress((void**)&ctx,  g_ctx);
    cudaGetSymbolAddress((void**)&x1,   g_x1);
    cudaGetSymbolAddress((void**)&h2,   g_h2);
    cudaGetSymbolAddress((void**)&ff1,  g_ff1);
    cudaGetSymbolAddress((void**)&wbuf, g_w);
    cudaGetSymbolAddress((void**)&bqkv, g_bqkv);

    float* rWqkv = wbuf;
    float* rWo   = rWqkv + Dm * DQKV;
    float* rW1   = rWo + Dm * Dm;
    float* rW2   = rW1 + Dm * DFFm;

    round_all_kernel<<<1184, 256>>>(Wq, Wk, Wv, Wo, W1, W2, bq, bk, bv, wbuf, bqkv);

    cudaFuncSetAttribute(tf32gemm_kernel<false, false, false>, cudaFuncAttributeMaxDynamicSharedMemorySize, GEMM_SMEM);
    cudaFuncSetAttribute(tf32gemm_kernel<false, true,  false>, cudaFuncAttributeMaxDynamicSharedMemorySize, GEMM_SMEM);
    cudaFuncSetAttribute(tf32gemm_kernel<true,  false, true >, cudaFuncAttributeMaxDynamicSharedMemorySize, GEMM_SMEM);

    ln_kernel<<<NT, 256>>>(x, ln1_g, ln1_b, h);

    tf32gemm_kernel<false, false, false><<<dim3(DQKV / 128, NT / 128), 256, GEMM_SMEM>>>(h, rWqkv, bqkv, nullptr, qkv, NT, DQKV, Dm);

    const int ATTN_SMEM = 6 * 64 * ATS * 4 + 256 * 4;   // 105472
    cudaFuncSetAttribute(attn_tc_kernel, cudaFuncAttributeMaxDynamicSharedMemorySize, ATTN_SMEM);
    attn_tc_kernel<<<dim3(Ss / 64, Hh, Bb), 256, ATTN_SMEM>>>(qkv, am, ctx);

    dim3 gD(Dm / 128, NT / 128);
    tf32gemm_kernel<false, true, false><<<gD, 256, GEMM_SMEM>>>(ctx, rWo, bo, x, x1, NT, Dm, Dm);

    ln_kernel<<<NT, 256>>>(x1, ln2_g, ln2_b, h2);

    tf32gemm_kernel<true, false, true><<<dim3(DFFm / 128, NT / 128), 256, GEMM_SMEM>>>(h2, rW1, b1, nullptr, ff1, NT, DFFm, Dm);
    tf32gemm_kernel<false, true, false><<<gD, 256, GEMM_SMEM>>>(ff1, rW2, b2, x1, out, NT, Dm, DFFm);
}

// round 15
// speedup vs baseline: 1.1056x; 1.1056x over previous
#include <cuda_runtime.h>
#include <math.h>
#include <stdint.h>

#define Dm   768
#define Hh   12
#define HDm  64
#define DFFm 3072
#define Bb   2
#define Ss   4096
#define NT   (Bb*Ss)
#define DQKV (3*Dm)   // 2304

// ---- scratch ----
__device__ float g_h   [NT*Dm];
__device__ float g_qkv [NT*DQKV];
__device__ float g_ctx [NT*Dm];
__device__ float g_x1  [NT*Dm];
__device__ float g_h2  [NT*Dm];
__device__ float g_ff1 [NT*DFFm];
__device__ float g_w   [Dm*DQKV + Dm*Dm + 2*Dm*DFFm];
__device__ float g_bqkv[DQKV];

// ---------- helpers ----------
__device__ __forceinline__ uint32_t f2tf32(float f) {
    uint32_t r;
    asm("cvt.rna.tf32.f32 %0, %1;" : "=r"(r) : "f"(f));
    return r;
}
__device__ __forceinline__ float rtf(float f) { return __uint_as_float(f2tf32(f)); }

__device__ __forceinline__ void cp_async16(void* smem, const void* gmem) {
    uint32_t s = (uint32_t)__cvta_generic_to_shared(smem);
    asm volatile("cp.async.cg.shared.global [%0], [%1], 16;" :: "r"(s), "l"(gmem));
}

__device__ __forceinline__ void ldsm_x4(uint32_t& r0, uint32_t& r1, uint32_t& r2, uint32_t& r3, uint32_t addr) {
    asm volatile("ldmatrix.sync.aligned.m8n8.x4.shared.b16 {%0,%1,%2,%3}, [%4];"
        : "=r"(r0), "=r"(r1), "=r"(r2), "=r"(r3) : "r"(addr));
}
__device__ __forceinline__ void ldsm_x2(uint32_t& r0, uint32_t& r1, uint32_t addr) {
    asm volatile("ldmatrix.sync.aligned.m8n8.x2.shared.b16 {%0,%1}, [%2];"
        : "=r"(r0), "=r"(r1) : "r"(addr));
}

// ============================ fused rounding pre-pass ============================
#define WQKV4 (Dm * DQKV / 4)
#define WO4   (Dm * Dm / 4)
#define WF4   (Dm * DFFm / 4)
#define TOT4  (WQKV4 + WO4 + 2 * WF4 + DQKV / 4)

__global__ void round_all_kernel(const float* __restrict__ Wq, const float* __restrict__ Wk,
                                 const float* __restrict__ Wv, const float* __restrict__ Wo,
                                 const float* __restrict__ W1, const float* __restrict__ W2,
                                 const float* __restrict__ bq, const float* __restrict__ bk,
                                 const float* __restrict__ bv,
                                 float* __restrict__ wdst, float* __restrict__ bdst) {
    const int SRC4 = Dm / 4;
    const int DST4 = DQKV / 4;
    for (int i = blockIdx.x * blockDim.x + threadIdx.x; i < TOT4; i += gridDim.x * blockDim.x) {
        float4 v; float4* dp;
        if (i < WQKV4) {
            int r = i / DST4, c = i % DST4;
            const float* src = (c < SRC4) ? Wq : (c < 2 * SRC4) ? Wk : Wv;
            int cl = (c >= 2 * SRC4) ? c - 2 * SRC4 : (c >= SRC4) ? c - SRC4 : c;
            v = ((const float4*)src)[r * SRC4 + cl];
            dp = (float4*)wdst + i;
        } else if (i < WQKV4 + WO4) {
            v = ((const float4*)Wo)[i - WQKV4];
            dp = (float4*)wdst + i;
        } else if (i < WQKV4 + WO4 + WF4) {
            v = ((const float4*)W1)[i - WQKV4 - WO4];
            dp = (float4*)wdst + i;
        } else if (i < WQKV4 + WO4 + 2 * WF4) {
            v = ((const float4*)W2)[i - WQKV4 - WO4 - WF4];
            dp = (float4*)wdst + i;
        } else {
            int c = i - (WQKV4 + WO4 + 2 * WF4);
            const float* src = (c < SRC4) ? bq : (c < 2 * SRC4) ? bk : bv;
            int cl = (c >= 2 * SRC4) ? c - 2 * SRC4 : (c >= SRC4) ? c - SRC4 : c;
            ((float4*)bdst)[c] = ((const float4*)src)[cl];
            continue;
        }
        v.x = rtf(v.x); v.y = rtf(v.y); v.z = rtf(v.z); v.w = rtf(v.w);
        *dp = v;
    }
}

// ============================ LayerNorm (tf32-rounded output) ============================
__global__ void ln_kernel(const float* __restrict__ x,
                          const float* __restrict__ g,
                          const float* __restrict__ b,
                          float* __restrict__ out) {
    int row = blockIdx.x;
    const float* xr = x + (size_t)row * Dm;
    int tid = threadIdx.x;
    float v0 = xr[tid], v1 = xr[tid + 256], v2 = xr[tid + 512];
    float s  = v0 + v1 + v2;
    float s2 = v0*v0 + v1*v1 + v2*v2;
    #pragma unroll
    for (int o = 16; o; o >>= 1) {
        s  += __shfl_xor_sync(0xffffffffu, s,  o);
        s2 += __shfl_xor_sync(0xffffffffu, s2, o);
    }
    __shared__ float ws[8], ws2[8];
    int w = tid >> 5, l = tid & 31;
    if (l == 0) { ws[w] = s; ws2[w] = s2; }
    __syncthreads();
    __shared__ float smu, srs;
    if (w == 0) {
        s  = (l < 8) ? ws[l]  : 0.f;
        s2 = (l < 8) ? ws2[l] : 0.f;
        #pragma unroll
        for (int o = 4; o; o >>= 1) {
            s  += __shfl_xor_sync(0xffffffffu, s,  o);
            s2 += __shfl_xor_sync(0xffffffffu, s2, o);
        }
        if (l == 0) {
            float mu  = s / Dm;
            float var = fmaxf(s2 / Dm - mu * mu, 0.f);
            smu = mu;
            srs = rsqrtf(var + 1e-5f);
        }
    }
    __syncthreads();
    float mu = smu, rs = srs;
    float* outr = out + (size_t)row * Dm;
    outr[tid]       = rtf((v0 - mu) * rs * g[tid]       + b[tid]);
    outr[tid + 256] = rtf((v1 - mu) * rs * g[tid + 256] + b[tid + 256]);
    outr[tid + 512] = rtf((v2 - mu) * rs * g[tid + 512] + b[tid + 512]);
}

// ============================ TF32 tensor-core GEMM (cp.async 2-stage, ldmatrix A) ============================
#define ASTR 36
#define BSTR 136
#define A_WORDS (128 * ASTR)
#define B_WORDS (32 * BSTR)
#define GEMM_SMEM (2 * (A_WORDS + B_WORDS) * 4)

template<bool RELU, bool RES, bool RNDC>
__global__ __launch_bounds__(256, 2)
void tf32gemm_kernel(const float* __restrict__ A,
                     const float* __restrict__ B,
                     const float* __restrict__ bias,
                     const float* __restrict__ res,
                     float* __restrict__ C,
                     int M, int N, int K) {
    extern __shared__ uint32_t sh[];
    uint32_t* AsBase = sh;
    uint32_t* BsBase = sh + 2 * A_WORDS;

    int tid  = threadIdx.x;
    int lane = tid & 31;
    int warp = tid >> 5;
    int warp_m = warp & 1;
    int warp_n = warp >> 1;
    int grp = lane >> 2;
    int thr = lane & 3;

    int row0 = blockIdx.y * 128;
    int col0 = blockIdx.x * 128;

    int aoff = (warp_m * 64 + (lane & 15)) * ASTR + ((lane >> 4) << 2);

    float c[4][4][4];
    #pragma unroll
    for (int mt = 0; mt < 4; mt++)
        #pragma unroll
        for (int nt = 0; nt < 4; nt++)
            #pragma unroll
            for (int i = 0; i < 4; i++) c[mt][nt][i] = 0.f;

    auto load_tile = [&](int k0, int stg) {
        uint32_t* Ad = AsBase + stg * A_WORDS;
        uint32_t* Bd = BsBase + stg * B_WORDS;
        #pragma unroll
        for (int it = 0; it < 4; it++) {
            int i = it * 256 + tid;
            int r = i >> 3, kc = (i & 7) * 4;
            cp_async16(&Ad[r * ASTR + kc], A + (size_t)(row0 + r) * K + k0 + kc);
        }
        #pragma unroll
        for (int it = 0; it < 4; it++) {
            int i = it * 256 + tid;
            int kr = i >> 5, nc = (i & 31) * 4;
            cp_async16(&Bd[kr * BSTR + nc], B + (size_t)(k0 + kr) * N + col0 + nc);
        }
        asm volatile("cp.async.commit_group;" ::: "memory");
    };

    int NK = K >> 5;
    load_tile(0, 0);

    for (int i = 0; i < NK; i++) {
        if (i + 1 < NK) {
            load_tile((i + 1) << 5, (i + 1) & 1);
            asm volatile("cp.async.wait_group 1;" ::: "memory");
        } else {
            asm volatile("cp.async.wait_group 0;" ::: "memory");
        }
        __syncthreads();

        const uint32_t* As = AsBase + (i & 1) * A_WORDS;
        const uint32_t* Bs = BsBase + (i & 1) * B_WORDS;
        uint32_t asU = (uint32_t)__cvta_generic_to_shared(As);

        #pragma unroll
        for (int ks = 0; ks < 4; ks++) {
            int kb = ks * 8;
            uint32_t af[4][4];
            #pragma unroll
            for (int mt = 0; mt < 4; mt++) {
                uint32_t addr = asU + (uint32_t)(aoff + mt * 16 * ASTR + kb) * 4u;
                ldsm_x4(af[mt][0], af[mt][1], af[mt][2], af[mt][3], addr);
            }
            uint32_t bf[4][2];
            #pragma unroll
            for (int nt = 0; nt < 4; nt++) {
                int cc = warp_n * 32 + nt * 8 + grp;
                bf[nt][0] = Bs[(kb + thr) * BSTR + cc];
                bf[nt][1] = Bs[(kb + thr + 4) * BSTR + cc];
            }
            #pragma unroll
            for (int mt = 0; mt < 4; mt++)
                #pragma unroll
                for (int nt = 0; nt < 4; nt++) {
                    asm("mma.sync.aligned.m16n8k8.row.col.f32.tf32.tf32.f32 "
                        "{%0,%1,%2,%3}, {%4,%5,%6,%7}, {%8,%9}, {%0,%1,%2,%3};"
                        : "+f"(c[mt][nt][0]), "+f"(c[mt][nt][1]),
                          "+f"(c[mt][nt][2]), "+f"(c[mt][nt][3])
                        : "r"(af[mt][0]), "r"(af[mt][1]), "r"(af[mt][2]), "r"(af[mt][3]),
                          "r"(bf[nt][0]), "r"(bf[nt][1]));
                }
        }
        __syncthreads();
    }

    #pragma unroll
    for (int mt = 0; mt < 4; mt++) {
        int r = row0 + warp_m * 64 + mt * 16 + grp;
        #pragma unroll
        for (int nt = 0; nt < 4; nt++) {
            int cc = col0 + warp_n * 32 + nt * 8 + 2 * thr;
            float b0 = bias[cc], b1 = bias[cc + 1];
            float o0 = c[mt][nt][0] + b0, o1 = c[mt][nt][1] + b1;
            float o2 = c[mt][nt][2] + b0, o3 = c[mt][nt][3] + b1;
            if (RELU) {
                o0 = fmaxf(o0, 0.f); o1 = fmaxf(o1, 0.f);
                o2 = fmaxf(o2, 0.f); o3 = fmaxf(o3, 0.f);
            }
            if (RES) {
                const float* rp0 = res + (size_t)r * N + cc;
                const float* rp1 = res + (size_t)(r + 8) * N + cc;
                o0 += rp0[0]; o1 += rp0[1];
                o2 += rp1[0]; o3 += rp1[1];
            }
            if (RNDC) {
                o0 = rtf(o0); o1 = rtf(o1); o2 = rtf(o2); o3 = rtf(o3);
            }
            *(float2*)&C[(size_t)r * N + cc]       = make_float2(o0, o1);
            *(float2*)&C[(size_t)(r + 8) * N + cc] = make_float2(o2, o3);
        }
    }
}

// ============================ TF32 tensor-core flash attention ============================
// R13 shape (128 threads, 4 independent warps, 64-row Q tile) with:
//   - Q held in registers (staged once through Ps)
//   - K single-buffered (fill issued after S readers sync; covered by softmax+PV)
//   - V double-buffered (prefetch one tile ahead)
//   - smem 69.6 KB -> 3 CTA/SM
#define ATS 68
#define KV_WORDS (64 * ATS)

__global__ __launch_bounds__(128, 3)
void attn_tc_kernel(const float* __restrict__ QKV,
                    const int*   __restrict__ am,
                    float* __restrict__ O) {
    extern __shared__ uint32_t smx[];
    uint32_t* Ps = smx;                  // [64][ATS] (Q staging, then P)
    uint32_t* Ks = Ps + KV_WORDS;        // [64][ATS] single buffer
    uint32_t* Vs = Ks + KV_WORDS;        // [2][64][ATS]

    int tid  = threadIdx.x;
    int warp = tid >> 5;
    int lane = tid & 31;
    int grp  = lane >> 2;
    int thr  = lane & 3;

    int qt = gridDim.x - 1 - blockIdx.x;   // heavy tiles first
    int q0 = qt * 64;
    int h  = blockIdx.y;
    int b  = blockIdx.z;
    int r0 = warp * 16;

    uint32_t ksU = (uint32_t)__cvta_generic_to_shared(Ks);
    uint32_t psU = (uint32_t)__cvta_generic_to_shared(Ps);

    int aoff = (r0 + (lane & 15)) * ATS + ((lane >> 4) << 2);
    int koff = (lane & 7) * ATS + ((lane >> 3) & 1) * 4;

    const float* Qbase = QKV + ((size_t)(b * Ss + q0)) * DQKV + h * HDm;
    const float* Kbase = QKV + ((size_t)b * Ss) * DQKV + Dm + h * HDm;
    const float* Vbase = QKV + ((size_t)b * Ss) * DQKV + 2 * Dm + h * HDm;
    const int*   amb   = am + b * Ss;

    int ktiles = qt + 1;

    auto fill_V = [&](int kt, int stg) {
        const float* Vb = Vbase + (size_t)(kt * 64) * DQKV;
        uint32_t* Vd = Vs + stg * KV_WORDS;
        #pragma unroll
        for (int it = 0; it < 8; it++) {
            int i = it * 128 + tid;
            int r = i >> 4, c = (i & 15) * 4;
            cp_async16(&Vd[r * ATS + c], Vb + (size_t)r * DQKV + c);
        }
        asm volatile("cp.async.commit_group;" ::: "memory");
    };
    auto fill_K = [&](int kt) {
        const float* Kb = Kbase + (size_t)(kt * 64) * DQKV;
        #pragma unroll
        for (int it = 0; it < 8; it++) {
            int i = it * 128 + tid;
            int r = i >> 4, c = (i & 15) * 4;
            cp_async16(&Ks[r * ATS + c], Kb + (size_t)r * DQKV + c);
        }
        asm volatile("cp.async.commit_group;" ::: "memory");
    };

    fill_V(0, 0);
    fill_K(0);

    // stage Q through Ps, then pull A-fragments into registers (scale folds log2e)
    const float QSCALE = 0.125f * 1.44269504f;
    for (int i = tid; i < 64 * 16; i += 128) {
        int r = i >> 4, c = (i & 15) * 4;
        float4 v = *(const float4*)(Qbase + (size_t)r * DQKV + c);
        uint4 t;
        t.x = f2tf32(v.x * QSCALE); t.y = f2tf32(v.y * QSCALE);
        t.z = f2tf32(v.z * QSCALE); t.w = f2tf32(v.w * QSCALE);
        *(uint4*)&Ps[r * ATS + c] = t;
    }
    __syncthreads();
    uint32_t qa[8][4];
    #pragma unroll
    for (int ks = 0; ks < 8; ks++)
        ldsm_x4(qa[ks][0], qa[ks][1], qa[ks][2], qa[ks][3],
                psU + (uint32_t)(aoff + ks * 8) * 4u);
    __syncthreads();   // Ps now free for P

    float o[8][4];
    #pragma unroll
    for (int nc = 0; nc < 8; nc++)
        #pragma unroll
        for (int i = 0; i < 4; i++) o[nc][i] = 0.f;
    float m0 = -INFINITY, m1 = -INFINITY, l0 = 0.f, l1 = 0.f;

    int qg0 = q0 + r0 + grp;
    int qg1 = qg0 + 8;

    for (int kt = 0; kt < ktiles; kt++) {
        int k0 = kt * 64;
        asm volatile("cp.async.wait_group 0;" ::: "memory");   // K(kt), V(kt) done
        __syncthreads();
        if (kt + 1 < ktiles) fill_V(kt + 1, (kt + 1) & 1);     // V buf free (PV(kt-1) synced)

        const uint32_t* VsCur = Vs + (kt & 1) * KV_WORDS;

        // ---- S = Q K^T ----
        float s[8][4];
        #pragma unroll
        for (int nc = 0; nc < 8; nc++)
            #pragma unroll
            for (int i = 0; i < 4; i++) s[nc][i] = 0.f;

        #pragma unroll
        for (int ks = 0; ks < 8; ks++) {
            int kb = ks * 8;
            #pragma unroll
            for (int nc = 0; nc < 8; nc++) {
                uint32_t b0, b1;
                ldsm_x2(b0, b1, ksU + (uint32_t)(koff + nc * 8 * ATS + kb) * 4u);
                asm("mma.sync.aligned.m16n8k8.row.col.f32.tf32.tf32.f32 "
                    "{%0,%1,%2,%3}, {%4,%5,%6,%7}, {%8,%9}, {%0,%1,%2,%3};"
                    : "+f"(s[nc][0]), "+f"(s[nc][1]), "+f"(s[nc][2]), "+f"(s[nc][3])
                    : "r"(qa[ks][0]), "r"(qa[ks][1]), "r"(qa[ks][2]), "r"(qa[ks][3]),
                      "r"(b0), "r"(b1));
            }
        }
        __syncthreads();                                   // all warps done reading Ks
        if (kt + 1 < ktiles) fill_K(kt + 1);               // covered by softmax + PV

        // ---- mask ----
        #pragma unroll
        for (int nc = 0; nc < 8; nc++) {
            int ca = k0 + nc * 8 + 2 * thr;
            int cb = ca + 1;
            bool va = (amb[ca] != 0), vb = (amb[cb] != 0);
            if (!(ca <= qg0 && va)) s[nc][0] = -INFINITY;
            if (!(cb <= qg0 && vb)) s[nc][1] = -INFINITY;
            if (!(ca <= qg1 && va)) s[nc][2] = -INFINITY;
            if (!(cb <= qg1 && vb)) s[nc][3] = -INFINITY;
        }

        // ---- online softmax (base-2 domain) ----
        float t0 = -INFINITY, t1 = -INFINITY;
        #pragma unroll
        for (int nc = 0; nc < 8; nc++) {
            t0 = fmaxf(t0, fmaxf(s[nc][0], s[nc][1]));
            t1 = fmaxf(t1, fmaxf(s[nc][2], s[nc][3]));
        }
        t0 = fmaxf(t0, __shfl_xor_sync(0xffffffffu, t0, 1));
        t0 = fmaxf(t0, __shfl_xor_sync(0xffffffffu, t0, 2));
        t1 = fmaxf(t1, __shfl_xor_sync(0xffffffffu, t1, 1));
        t1 = fmaxf(t1, __shfl_xor_sync(0xffffffffu, t1, 2));

        float mn0 = fmaxf(m0, t0), mn1 = fmaxf(m1, t1);
        float al0 = (mn0 == -INFINITY) ? 1.f : exp2f(m0 - mn0);
        float al1 = (mn1 == -INFINITY) ? 1.f : exp2f(m1 - mn1);

        float ps0 = 0.f, ps1 = 0.f;
        #pragma unroll
        for (int nc = 0; nc < 8; nc++) {
            float p0 = (s[nc][0] == -INFINITY) ? 0.f : exp2f(s[nc][0] - mn0);
            float p1 = (s[nc][1] == -INFINITY) ? 0.f : exp2f(s[nc][1] - mn0);
            float p2 = (s[nc][2] == -INFINITY) ? 0.f : exp2f(s[nc][2] - mn1);
            float p3 = (s[nc][3] == -INFINITY) ? 0.f : exp2f(s[nc][3] - mn1);
            ps0 += p0 + p1;
            ps1 += p2 + p3;
            *(uint2*)&Ps[(r0 + grp) * ATS + nc * 8 + 2 * thr]     = make_uint2(__float_as_uint(p0), __float_as_uint(p1));
            *(uint2*)&Ps[(r0 + grp + 8) * ATS + nc * 8 + 2 * thr] = make_uint2(__float_as_uint(p2), __float_as_uint(p3));
        }
        ps0 += __shfl_xor_sync(0xffffffffu, ps0, 1);
        ps0 += __shfl_xor_sync(0xffffffffu, ps0, 2);
        ps1 += __shfl_xor_sync(0xffffffffu, ps1, 1);
        ps1 += __shfl_xor_sync(0xffffffffu, ps1, 2);

        l0 = l0 * al0 + ps0;
        l1 = l1 * al1 + ps1;
        m0 = mn0; m1 = mn1;

        #pragma unroll
        for (int nc = 0; nc < 8; nc++) {
            o[nc][0] *= al0; o[nc][1] *= al0;
            o[nc][2] *= al1; o[nc][3] *= al1;
        }
        __syncwarp();   // Ps rows r0..r0+15 are warp-local

        // ---- O += P V ----
        #pragma unroll
        for (int ks = 0; ks < 8; ks++) {
            int kb = ks * 8;
            uint32_t a0, a1, a2, a3;
            ldsm_x4(a0, a1, a2, a3, psU + (uint32_t)(aoff + kb) * 4u);
            #pragma unroll
            for (int nc = 0; nc < 8; nc++) {
                uint32_t b0 = VsCur[(kb + thr) * ATS + nc * 8 + grp];
                uint32_t b1 = VsCur[(kb + thr + 4) * ATS + nc * 8 + grp];
                asm("mma.sync.aligned.m16n8k8.row.col.f32.tf32.tf32.f32 "
                    "{%0,%1,%2,%3}, {%4,%5,%6,%7}, {%8,%9}, {%0,%1,%2,%3};"
                    : "+f"(o[nc][0]), "+f"(o[nc][1]), "+f"(o[nc][2]), "+f"(o[nc][3])
                    : "r"(a0), "r"(a1), "r"(a2), "r"(a3), "r"(b0), "r"(b1));
            }
        }
        // no trailing sync: next iteration's wait+sync orders buffer reuse
    }

    float rl0 = (l0 > 0.f) ? 1.f / l0 : 0.f;
    float rl1 = (l1 > 0.f) ? 1.f / l1 : 0.f;
    float* Ob = O + ((size_t)(b * Ss + q0)) * Dm + h * HDm;
    #pragma unroll
    for (int nc = 0; nc < 8; nc++) {
        int cc = nc * 8 + 2 * thr;
        *(float2*)(Ob + (size_t)(r0 + grp) * Dm + cc)     = make_float2(rtf(o[nc][0] * rl0), rtf(o[nc][1] * rl0));
        *(float2*)(Ob + (size_t)(r0 + grp + 8) * Dm + cc) = make_float2(rtf(o[nc][2] * rl1), rtf(o[nc][3] * rl1));
    }
}

// ============================ launch ============================
extern "C" void kernel_launch(void* const* d_in, const int* in_sizes, int n_in,
                              void* d_out, int out_size) {
    const float* x     = (const float*)d_in[0];
    const int*   am    = (const int*)  d_in[1];
    const float* ln1_g = (const float*)d_in[2];
    const float* ln1_b = (const float*)d_in[3];
    const float* ln2_g = (const float*)d_in[4];
    const float* ln2_b = (const float*)d_in[5];
    const float* Wq = (const float*)d_in[6];
    const float* bq = (const float*)d_in[7];
    const float* Wk = (const float*)d_in[8];
    const float* bk = (const float*)d_in[9];
    const float* Wv = (const float*)d_in[10];
    const float* bv = (const float*)d_in[11];
    const float* Wo = (const float*)d_in[12];
    const float* bo = (const float*)d_in[13];
    const float* W1 = (const float*)d_in[14];
    const float* b1 = (const float*)d_in[15];
    const float* W2 = (const float*)d_in[16];
    const float* b2 = (const float*)d_in[17];
    float* out = (float*)d_out;

    float *h, *qkv, *ctx, *x1, *h2, *ff1, *wbuf, *bqkv;
    cudaGetSymbolAddress((void**)&h,    g_h);
    cudaGetSymbolAddress((void**)&qkv,  g_qkv);
    cudaGetSymbolAddress((void**)&ctx,  g_ctx);
    cudaGetSymbolAddress((void**)&x1,   g_x1);
    cudaGetSymbolAddress((void**)&h2,   g_h2);
    cudaGetSymbolAddress((void**)&ff1,  g_ff1);
    cudaGetSymbolAddress((void**)&wbuf, g_w);
    cudaGetSymbolAddress((void**)&bqkv, g_bqkv);

    float* rWqkv = wbuf;
    float* rWo   = rWqkv + Dm * DQKV;
    float* rW1   = rWo + Dm * Dm;
    float* rW2   = rW1 + Dm * DFFm;

    round_all_kernel<<<1184, 256>>>(Wq, Wk, Wv, Wo, W1, W2, bq, bk, bv, wbuf, bqkv);

    cudaFuncSetAttribute(tf32gemm_kernel<false, false, false>, cudaFuncAttributeMaxDynamicSharedMemorySize, GEMM_SMEM);
    cudaFuncSetAttribute(tf32gemm_kernel<false, true,  false>, cudaFuncAttributeMaxDynamicSharedMemorySize, GEMM_SMEM);
    cudaFuncSetAttribute(tf32gemm_kernel<true,  false, true >, cudaFuncAttributeMaxDynamicSharedMemorySize, GEMM_SMEM);

    ln_kernel<<<NT, 256>>>(x, ln1_g, ln1_b, h);

    tf32gemm_kernel<false, false, false><<<dim3(DQKV / 128, NT / 128), 256, GEMM_SMEM>>>(h, rWqkv, bqkv, nullptr, qkv, NT, DQKV, Dm);

    const int ATTN_SMEM = 4 * 64 * ATS * 4;   // 69632 -> 3 CTA/SM
    cudaFuncSetAttribute(attn_tc_kernel, cudaFuncAttributeMaxDynamicSharedMemorySize, ATTN_SMEM);
    attn_tc_kernel<<<dim3(Ss / 64, Hh, Bb), 128, ATTN_SMEM>>>(qkv, am, ctx);

    dim3 gD(Dm / 128, NT / 128);
    tf32gemm_kernel<false, true, false><<<gD, 256, GEMM_SMEM>>>(ctx, rWo, bo, x, x1, NT, Dm, Dm);

    ln_kernel<<<NT, 256>>>(x1, ln2_g, ln2_b, h2);

    tf32gemm_kernel<true, false, true><<<dim3(DFFm / 128, NT / 128), 256, GEMM_SMEM>>>(h2, rW1, b1, nullptr, ff1, NT, DFFm, Dm);
    tf32gemm_kernel<false, true, false><<<gD, 256, GEMM_SMEM>>>(ff1, rW2, b2, x1, out, NT, Dm, DFFm);
}

// round 16
// speedup vs baseline: 1.1502x; 1.0403x over previous
#include <cuda_runtime.h>
#include <math.h>
#include <stdint.h>

#define Dm   768
#define Hh   12
#define HDm  64
#define DFFm 3072
#define Bb   2
#define Ss   4096
#define NT   (Bb*Ss)
#define DQKV (3*Dm)   // 2304

// ---- scratch ----
__device__ float g_h   [NT*Dm];
__device__ float g_qkv [NT*DQKV];
__device__ float g_ctx [NT*Dm];
__device__ float g_x1  [NT*Dm];
__device__ float g_h2  [NT*Dm];
__device__ float g_ff1 [NT*DFFm];
__device__ float g_w   [Dm*DQKV + Dm*Dm + 2*Dm*DFFm];
__device__ float g_bqkv[DQKV];

// ---------- helpers ----------
__device__ __forceinline__ uint32_t f2tf32(float f) {
    uint32_t r;
    asm("cvt.rna.tf32.f32 %0, %1;" : "=r"(r) : "f"(f));
    return r;
}
__device__ __forceinline__ float rtf(float f) { return __uint_as_float(f2tf32(f)); }

__device__ __forceinline__ void cp_async16(void* smem, const void* gmem) {
    uint32_t s = (uint32_t)__cvta_generic_to_shared(smem);
    asm volatile("cp.async.cg.shared.global [%0], [%1], 16;" :: "r"(s), "l"(gmem));
}

__device__ __forceinline__ void ldsm_x4(uint32_t& r0, uint32_t& r1, uint32_t& r2, uint32_t& r3, uint32_t addr) {
    asm volatile("ldmatrix.sync.aligned.m8n8.x4.shared.b16 {%0,%1,%2,%3}, [%4];"
        : "=r"(r0), "=r"(r1), "=r"(r2), "=r"(r3) : "r"(addr));
}

// ============================ fused rounding pre-pass ============================
#define WQKV4 (Dm * DQKV / 4)
#define WO4   (Dm * Dm / 4)
#define WF4   (Dm * DFFm / 4)
#define TOT4  (WQKV4 + WO4 + 2 * WF4 + DQKV / 4)

__global__ void round_all_kernel(const float* __restrict__ Wq, const float* __restrict__ Wk,
                                 const float* __restrict__ Wv, const float* __restrict__ Wo,
                                 const float* __restrict__ W1, const float* __restrict__ W2,
                                 const float* __restrict__ bq, const float* __restrict__ bk,
                                 const float* __restrict__ bv,
                                 float* __restrict__ wdst, float* __restrict__ bdst) {
    const int SRC4 = Dm / 4;
    const int DST4 = DQKV / 4;
    for (int i = blockIdx.x * blockDim.x + threadIdx.x; i < TOT4; i += gridDim.x * blockDim.x) {
        float4 v; float4* dp;
        if (i < WQKV4) {
            int r = i / DST4, c = i % DST4;
            const float* src = (c < SRC4) ? Wq : (c < 2 * SRC4) ? Wk : Wv;
            int cl = (c >= 2 * SRC4) ? c - 2 * SRC4 : (c >= SRC4) ? c - SRC4 : c;
            v = ((const float4*)src)[r * SRC4 + cl];
            dp = (float4*)wdst + i;
        } else if (i < WQKV4 + WO4) {
            v = ((const float4*)Wo)[i - WQKV4];
            dp = (float4*)wdst + i;
        } else if (i < WQKV4 + WO4 + WF4) {
            v = ((const float4*)W1)[i - WQKV4 - WO4];
            dp = (float4*)wdst + i;
        } else if (i < WQKV4 + WO4 + 2 * WF4) {
            v = ((const float4*)W2)[i - WQKV4 - WO4 - WF4];
            dp = (float4*)wdst + i;
        } else {
            int c = i - (WQKV4 + WO4 + 2 * WF4);
            const float* src = (c < SRC4) ? bq : (c < 2 * SRC4) ? bk : bv;
            int cl = (c >= 2 * SRC4) ? c - 2 * SRC4 : (c >= SRC4) ? c - SRC4 : c;
            ((float4*)bdst)[c] = ((const float4*)src)[cl];
            continue;
        }
        v.x = rtf(v.x); v.y = rtf(v.y); v.z = rtf(v.z); v.w = rtf(v.w);
        *dp = v;
    }
}

// ============================ LayerNorm (tf32-rounded output) ============================
__global__ void ln_kernel(const float* __restrict__ x,
                          const float* __restrict__ g,
                          const float* __restrict__ b,
                          float* __restrict__ out) {
    int row = blockIdx.x;
    const float* xr = x + (size_t)row * Dm;
    int tid = threadIdx.x;
    float v0 = xr[tid], v1 = xr[tid + 256], v2 = xr[tid + 512];
    float s  = v0 + v1 + v2;
    float s2 = v0*v0 + v1*v1 + v2*v2;
    #pragma unroll
    for (int o = 16; o; o >>= 1) {
        s  += __shfl_xor_sync(0xffffffffu, s,  o);
        s2 += __shfl_xor_sync(0xffffffffu, s2, o);
    }
    __shared__ float ws[8], ws2[8];
    int w = tid >> 5, l = tid & 31;
    if (l == 0) { ws[w] = s; ws2[w] = s2; }
    __syncthreads();
    __shared__ float smu, srs;
    if (w == 0) {
        s  = (l < 8) ? ws[l]  : 0.f;
        s2 = (l < 8) ? ws2[l] : 0.f;
        #pragma unroll
        for (int o = 4; o; o >>= 1) {
            s  += __shfl_xor_sync(0xffffffffu, s,  o);
            s2 += __shfl_xor_sync(0xffffffffu, s2, o);
        }
        if (l == 0) {
            float mu  = s / Dm;
            float var = fmaxf(s2 / Dm - mu * mu, 0.f);
            smu = mu;
            srs = rsqrtf(var + 1e-5f);
        }
    }
    __syncthreads();
    float mu = smu, rs = srs;
    float* outr = out + (size_t)row * Dm;
    outr[tid]       = rtf((v0 - mu) * rs * g[tid]       + b[tid]);
    outr[tid + 256] = rtf((v1 - mu) * rs * g[tid + 256] + b[tid + 256]);
    outr[tid + 512] = rtf((v2 - mu) * rs * g[tid + 512] + b[tid + 512]);
}

// ============================ TF32 tensor-core GEMM (cp.async 2-stage, ldmatrix A) ============================
#define ASTR 36
#define BSTR 136
#define A_WORDS (128 * ASTR)
#define B_WORDS (32 * BSTR)
#define GEMM_SMEM (2 * (A_WORDS + B_WORDS) * 4)

template<bool RELU, bool RES, bool RNDC>
__global__ __launch_bounds__(256, 2)
void tf32gemm_kernel(const float* __restrict__ A,
                     const float* __restrict__ B,
                     const float* __restrict__ bias,
                     const float* __restrict__ res,
                     float* __restrict__ C,
                     int M, int N, int K) {
    extern __shared__ uint32_t sh[];
    uint32_t* AsBase = sh;
    uint32_t* BsBase = sh + 2 * A_WORDS;

    int tid  = threadIdx.x;
    int lane = tid & 31;
    int warp = tid >> 5;
    int warp_m = warp & 1;
    int warp_n = warp >> 1;
    int grp = lane >> 2;
    int thr = lane & 3;

    int row0 = blockIdx.y * 128;
    int col0 = blockIdx.x * 128;

    int aoff = (warp_m * 64 + (lane & 15)) * ASTR + ((lane >> 4) << 2);

    float c[4][4][4];
    #pragma unroll
    for (int mt = 0; mt < 4; mt++)
        #pragma unroll
        for (int nt = 0; nt < 4; nt++)
            #pragma unroll
            for (int i = 0; i < 4; i++) c[mt][nt][i] = 0.f;

    auto load_tile = [&](int k0, int stg) {
        uint32_t* Ad = AsBase + stg * A_WORDS;
        uint32_t* Bd = BsBase + stg * B_WORDS;
        #pragma unroll
        for (int it = 0; it < 4; it++) {
            int i = it * 256 + tid;
            int r = i >> 3, kc = (i & 7) * 4;
            cp_async16(&Ad[r * ASTR + kc], A + (size_t)(row0 + r) * K + k0 + kc);
        }
        #pragma unroll
        for (int it = 0; it < 4; it++) {
            int i = it * 256 + tid;
            int kr = i >> 5, nc = (i & 31) * 4;
            cp_async16(&Bd[kr * BSTR + nc], B + (size_t)(k0 + kr) * N + col0 + nc);
        }
        asm volatile("cp.async.commit_group;" ::: "memory");
    };

    int NK = K >> 5;
    load_tile(0, 0);

    for (int i = 0; i < NK; i++) {
        if (i + 1 < NK) {
            load_tile((i + 1) << 5, (i + 1) & 1);
            asm volatile("cp.async.wait_group 1;" ::: "memory");
        } else {
            asm volatile("cp.async.wait_group 0;" ::: "memory");
        }
        __syncthreads();

        const uint32_t* As = AsBase + (i & 1) * A_WORDS;
        const uint32_t* Bs = BsBase + (i & 1) * B_WORDS;
        uint32_t asU = (uint32_t)__cvta_generic_to_shared(As);

        #pragma unroll
        for (int ks = 0; ks < 4; ks++) {
            int kb = ks * 8;
            uint32_t af[4][4];
            #pragma unroll
            for (int mt = 0; mt < 4; mt++) {
                uint32_t addr = asU + (uint32_t)(aoff + mt * 16 * ASTR + kb) * 4u;
                ldsm_x4(af[mt][0], af[mt][1], af[mt][2], af[mt][3], addr);
            }
            uint32_t bf[4][2];
            #pragma unroll
            for (int nt = 0; nt < 4; nt++) {
                int cc = warp_n * 32 + nt * 8 + grp;
                bf[nt][0] = Bs[(kb + thr) * BSTR + cc];
                bf[nt][1] = Bs[(kb + thr + 4) * BSTR + cc];
            }
            #pragma unroll
            for (int mt = 0; mt < 4; mt++)
                #pragma unroll
                for (int nt = 0; nt < 4; nt++) {
                    asm("mma.sync.aligned.m16n8k8.row.col.f32.tf32.tf32.f32 "
                        "{%0,%1,%2,%3}, {%4,%5,%6,%7}, {%8,%9}, {%0,%1,%2,%3};"
                        : "+f"(c[mt][nt][0]), "+f"(c[mt][nt][1]),
                          "+f"(c[mt][nt][2]), "+f"(c[mt][nt][3])
                        : "r"(af[mt][0]), "r"(af[mt][1]), "r"(af[mt][2]), "r"(af[mt][3]),
                          "r"(bf[nt][0]), "r"(bf[nt][1]));
                }
        }
        __syncthreads();
    }

    #pragma unroll
    for (int mt = 0; mt < 4; mt++) {
        int r = row0 + warp_m * 64 + mt * 16 + grp;
        #pragma unroll
        for (int nt = 0; nt < 4; nt++) {
            int cc = col0 + warp_n * 32 + nt * 8 + 2 * thr;
            float b0 = bias[cc], b1 = bias[cc + 1];
            float o0 = c[mt][nt][0] + b0, o1 = c[mt][nt][1] + b1;
            float o2 = c[mt][nt][2] + b0, o3 = c[mt][nt][3] + b1;
            if (RELU) {
                o0 = fmaxf(o0, 0.f); o1 = fmaxf(o1, 0.f);
                o2 = fmaxf(o2, 0.f); o3 = fmaxf(o3, 0.f);
            }
            if (RES) {
                const float* rp0 = res + (size_t)r * N + cc;
                const float* rp1 = res + (size_t)(r + 8) * N + cc;
                o0 += rp0[0]; o1 += rp0[1];
                o2 += rp1[0]; o3 += rp1[1];
            }
            if (RNDC) {
                o0 = rtf(o0); o1 = rtf(o1); o2 = rtf(o2); o3 = rtf(o3);
            }
            *(float2*)&C[(size_t)r * N + cc]       = make_float2(o0, o1);
            *(float2*)&C[(size_t)(r + 8) * N + cc] = make_float2(o2, o3);
        }
    }
}

// ============================ TF32 tensor-core flash attention ============================
// R15 structure; ATS=72 (conflict-free V loads), mask in smem, paired ldsm.x4 K-frags.
#define ATS 72
#define KV_WORDS (64 * ATS)

__global__ __launch_bounds__(128, 3)
void attn_tc_kernel(const float* __restrict__ QKV,
                    const int*   __restrict__ am,
                    float* __restrict__ O) {
    extern __shared__ uint32_t smx[];
    uint32_t* Ps = smx;                  // [64][ATS] (Q staging, then P)
    uint32_t* Ks = Ps + KV_WORDS;        // [64][ATS] single buffer
    uint32_t* Vs = Ks + KV_WORDS;        // [2][64][ATS]
    uint32_t* AmS = Vs + 2 * KV_WORDS;   // [2][64] ints

    int tid  = threadIdx.x;
    int warp = tid >> 5;
    int lane = tid & 31;
    int grp  = lane >> 2;
    int thr  = lane & 3;

    int qt = gridDim.x - 1 - blockIdx.x;   // heavy tiles first
    int q0 = qt * 64;
    int h  = blockIdx.y;
    int b  = blockIdx.z;
    int r0 = warp * 16;

    uint32_t ksU = (uint32_t)__cvta_generic_to_shared(Ks);
    uint32_t psU = (uint32_t)__cvta_generic_to_shared(Ps);

    int aoff  = (r0 + (lane & 15)) * ATS + ((lane >> 4) << 2);
    // paired K-frag ldsm.x4: (rows nc | kb), (rows nc | kb+4), (rows nc+1 | kb), (rows nc+1 | kb+4)
    int koff4 = ((lane & 7) + ((lane >> 4) << 3)) * ATS + (((lane >> 3) & 1) << 2);

    const float* Qbase = QKV + ((size_t)(b * Ss + q0)) * DQKV + h * HDm;
    const float* Kbase = QKV + ((size_t)b * Ss) * DQKV + Dm + h * HDm;
    const float* Vbase = QKV + ((size_t)b * Ss) * DQKV + 2 * Dm + h * HDm;
    const int*   amb   = am + b * Ss;

    int ktiles = qt + 1;

    auto fill_V = [&](int kt, int stg) {
        const float* Vb = Vbase + (size_t)(kt * 64) * DQKV;
        uint32_t* Vd = Vs + stg * KV_WORDS;
        #pragma unroll
        for (int it = 0; it < 8; it++) {
            int i = it * 128 + tid;
            int r = i >> 4, c = (i & 15) * 4;
            cp_async16(&Vd[r * ATS + c], Vb + (size_t)r * DQKV + c);
        }
        if (tid < 16)
            cp_async16(&AmS[stg * 64 + tid * 4], amb + kt * 64 + tid * 4);
        asm volatile("cp.async.commit_group;" ::: "memory");
    };
    auto fill_K = [&](int kt) {
        const float* Kb = Kbase + (size_t)(kt * 64) * DQKV;
        #pragma unroll
        for (int it = 0; it < 8; it++) {
            int i = it * 128 + tid;
            int r = i >> 4, c = (i & 15) * 4;
            cp_async16(&Ks[r * ATS + c], Kb + (size_t)r * DQKV + c);
        }
        asm volatile("cp.async.commit_group;" ::: "memory");
    };

    fill_V(0, 0);
    fill_K(0);

    // stage Q through Ps, then pull A-fragments into registers (scale folds log2e)
    const float QSCALE = 0.125f * 1.44269504f;
    for (int i = tid; i < 64 * 16; i += 128) {
        int r = i >> 4, c = (i & 15) * 4;
        float4 v = *(const float4*)(Qbase + (size_t)r * DQKV + c);
        uint4 t;
        t.x = f2tf32(v.x * QSCALE); t.y = f2tf32(v.y * QSCALE);
        t.z = f2tf32(v.z * QSCALE); t.w = f2tf32(v.w * QSCALE);
        *(uint4*)&Ps[r * ATS + c] = t;
    }
    __syncthreads();
    uint32_t qa[8][4];
    #pragma unroll
    for (int ks = 0; ks < 8; ks++)
        ldsm_x4(qa[ks][0], qa[ks][1], qa[ks][2], qa[ks][3],
                psU + (uint32_t)(aoff + ks * 8) * 4u);
    __syncthreads();   // Ps now free for P

    float o[8][4];
    #pragma unroll
    for (int nc = 0; nc < 8; nc++)
        #pragma unroll
        for (int i = 0; i < 4; i++) o[nc][i] = 0.f;
    float m0 = -INFINITY, m1 = -INFINITY, l0 = 0.f, l1 = 0.f;

    int qg0 = q0 + r0 + grp;
    int qg1 = qg0 + 8;

    for (int kt = 0; kt < ktiles; kt++) {
        int k0 = kt * 64;
        asm volatile("cp.async.wait_group 0;" ::: "memory");
        __syncthreads();
        if (kt + 1 < ktiles) fill_V(kt + 1, (kt + 1) & 1);

        const uint32_t* VsCur = Vs + (kt & 1) * KV_WORDS;
        const int* amS = (const int*)(AmS + (kt & 1) * 64);

        // ---- S = Q K^T ----
        float s[8][4];
        #pragma unroll
        for (int nc = 0; nc < 8; nc++)
            #pragma unroll
            for (int i = 0; i < 4; i++) s[nc][i] = 0.f;

        #pragma unroll
        for (int ks = 0; ks < 8; ks++) {
            int kb = ks * 8;
            #pragma unroll
            for (int p = 0; p < 4; p++) {
                uint32_t b0, b1, b2, b3;
                ldsm_x4(b0, b1, b2, b3, ksU + (uint32_t)(koff4 + p * 16 * ATS + kb) * 4u);
                asm("mma.sync.aligned.m16n8k8.row.col.f32.tf32.tf32.f32 "
                    "{%0,%1,%2,%3}, {%4,%5,%6,%7}, {%8,%9}, {%0,%1,%2,%3};"
                    : "+f"(s[p*2][0]), "+f"(s[p*2][1]), "+f"(s[p*2][2]), "+f"(s[p*2][3])
                    : "r"(qa[ks][0]), "r"(qa[ks][1]), "r"(qa[ks][2]), "r"(qa[ks][3]),
                      "r"(b0), "r"(b1));
                asm("mma.sync.aligned.m16n8k8.row.col.f32.tf32.tf32.f32 "
                    "{%0,%1,%2,%3}, {%4,%5,%6,%7}, {%8,%9}, {%0,%1,%2,%3};"
                    : "+f"(s[p*2+1][0]), "+f"(s[p*2+1][1]), "+f"(s[p*2+1][2]), "+f"(s[p*2+1][3])
                    : "r"(qa[ks][0]), "r"(qa[ks][1]), "r"(qa[ks][2]), "r"(qa[ks][3]),
                      "r"(b2), "r"(b3));
            }
        }
        __syncthreads();                                   // Ks readers done
        if (kt + 1 < ktiles) fill_K(kt + 1);               // covered by softmax + PV

        // ---- mask (am from smem) ----
        #pragma unroll
        for (int nc = 0; nc < 8; nc++) {
            int cl = nc * 8 + 2 * thr;
            int ca = k0 + cl;
            int cb = ca + 1;
            bool va = (amS[cl] != 0), vb = (amS[cl + 1] != 0);
            if (!(ca <= qg0 && va)) s[nc][0] = -INFINITY;
            if (!(cb <= qg0 && vb)) s[nc][1] = -INFINITY;
            if (!(ca <= qg1 && va)) s[nc][2] = -INFINITY;
            if (!(cb <= qg1 && vb)) s[nc][3] = -INFINITY;
        }

        // ---- online softmax (base-2 domain; exp2(-inf - m) = 0 naturally) ----
        float t0 = -INFINITY, t1 = -INFINITY;
        #pragma unroll
        for (int nc = 0; nc < 8; nc++) {
            t0 = fmaxf(t0, fmaxf(s[nc][0], s[nc][1]));
            t1 = fmaxf(t1, fmaxf(s[nc][2], s[nc][3]));
        }
        t0 = fmaxf(t0, __shfl_xor_sync(0xffffffffu, t0, 1));
        t0 = fmaxf(t0, __shfl_xor_sync(0xffffffffu, t0, 2));
        t1 = fmaxf(t1, __shfl_xor_sync(0xffffffffu, t1, 1));
        t1 = fmaxf(t1, __shfl_xor_sync(0xffffffffu, t1, 2));

        float mn0 = fmaxf(m0, t0), mn1 = fmaxf(m1, t1);
        float al0 = (mn0 == -INFINITY) ? 1.f : exp2f(m0 - mn0);
        float al1 = (mn1 == -INFINITY) ? 1.f : exp2f(m1 - mn1);
        bool any0 = (mn0 != -INFINITY), any1 = (mn1 != -INFINITY);

        float ps0 = 0.f, ps1 = 0.f;
        #pragma unroll
        for (int nc = 0; nc < 8; nc++) {
            float p0 = any0 ? exp2f(s[nc][0] - mn0) : 0.f;
            float p1 = any0 ? exp2f(s[nc][1] - mn0) : 0.f;
            float p2 = any1 ? exp2f(s[nc][2] - mn1) : 0.f;
            float p3 = any1 ? exp2f(s[nc][3] - mn1) : 0.f;
            ps0 += p0 + p1;
            ps1 += p2 + p3;
            *(uint2*)&Ps[(r0 + grp) * ATS + nc * 8 + 2 * thr]     = make_uint2(__float_as_uint(p0), __float_as_uint(p1));
            *(uint2*)&Ps[(r0 + grp + 8) * ATS + nc * 8 + 2 * thr] = make_uint2(__float_as_uint(p2), __float_as_uint(p3));
        }
        ps0 += __shfl_xor_sync(0xffffffffu, ps0, 1);
        ps0 += __shfl_xor_sync(0xffffffffu, ps0, 2);
        ps1 += __shfl_xor_sync(0xffffffffu, ps1, 1);
        ps1 += __shfl_xor_sync(0xffffffffu, ps1, 2);

        l0 = l0 * al0 + ps0;
        l1 = l1 * al1 + ps1;
        m0 = mn0; m1 = mn1;

        #pragma unroll
        for (int nc = 0; nc < 8; nc++) {
            o[nc][0] *= al0; o[nc][1] *= al0;
            o[nc][2] *= al1; o[nc][3] *= al1;
        }
        __syncwarp();   // Ps rows r0..r0+15 are warp-local

        // ---- O += P V (conflict-free with ATS=72) ----
        #pragma unroll
        for (int ks = 0; ks < 8; ks++) {
            int kb = ks * 8;
            uint32_t a0, a1, a2, a3;
            ldsm_x4(a0, a1, a2, a3, psU + (uint32_t)(aoff + kb) * 4u);
            #pragma unroll
            for (int nc = 0; nc < 8; nc++) {
                uint32_t b0 = VsCur[(kb + thr) * ATS + nc * 8 + grp];
                uint32_t b1 = VsCur[(kb + thr + 4) * ATS + nc * 8 + grp];
                asm("mma.sync.aligned.m16n8k8.row.col.f32.tf32.tf32.f32 "
                    "{%0,%1,%2,%3}, {%4,%5,%6,%7}, {%8,%9}, {%0,%1,%2,%3};"
                    : "+f"(o[nc][0]), "+f"(o[nc][1]), "+f"(o[nc][2]), "+f"(o[nc][3])
                    : "r"(a0), "r"(a1), "r"(a2), "r"(a3), "r"(b0), "r"(b1));
            }
        }
        // no trailing sync: next iteration's wait+sync orders buffer reuse
    }

    float rl0 = (l0 > 0.f) ? 1.f / l0 : 0.f;
    float rl1 = (l1 > 0.f) ? 1.f / l1 : 0.f;
    float* Ob = O + ((size_t)(b * Ss + q0)) * Dm + h * HDm;
    #pragma unroll
    for (int nc = 0; nc < 8; nc++) {
        int cc = nc * 8 + 2 * thr;
        *(float2*)(Ob + (size_t)(r0 + grp) * Dm + cc)     = make_float2(rtf(o[nc][0] * rl0), rtf(o[nc][1] * rl0));
        *(float2*)(Ob + (size_t)(r0 + grp + 8) * Dm + cc) = make_float2(rtf(o[nc][2] * rl1), rtf(o[nc][3] * rl1));
    }
}

// ============================ launch ============================
extern "C" void kernel_launch(void* const* d_in, const int* in_sizes, int n_in,
                              void* d_out, int out_size) {
    const float* x     = (const float*)d_in[0];
    const int*   am    = (const int*)  d_in[1];
    const float* ln1_g = (const float*)d_in[2];
    const float* ln1_b = (const float*)d_in[3];
    const float* ln2_g = (const float*)d_in[4];
    const float* ln2_b = (const float*)d_in[5];
    const float* Wq = (const float*)d_in[6];
    const float* bq = (const float*)d_in[7];
    const float* Wk = (const float*)d_in[8];
    const float* bk = (const float*)d_in[9];
    const float* Wv = (const float*)d_in[10];
    const float* bv = (const float*)d_in[11];
    const float* Wo = (const float*)d_in[12];
    const float* bo = (const float*)d_in[13];
    const float* W1 = (const float*)d_in[14];
    const float* b1 = (const float*)d_in[15];
    const float* W2 = (const float*)d_in[16];
    const float* b2 = (const float*)d_in[17];
    float* out = (float*)d_out;

    float *h, *qkv, *ctx, *x1, *h2, *ff1, *wbuf, *bqkv;
    cudaGetSymbolAddress((void**)&h,    g_h);
    cudaGetSymbolAddress((void**)&qkv,  g_qkv);
    cudaGetSymbolAddress((void**)&ctx,  g_ctx);
    cudaGetSymbolAddress((void**)&x1,   g_x1);
    cudaGetSymbolAddress((void**)&h2,   g_h2);
    cudaGetSymbolAddress((void**)&ff1,  g_ff1);
    cudaGetSymbolAddress((void**)&wbuf, g_w);
    cudaGetSymbolAddress((void**)&bqkv, g_bqkv);

    float* rWqkv = wbuf;
    float* rWo   = rWqkv + Dm * DQKV;
    float* rW1   = rWo + Dm * Dm;
    float* rW2   = rW1 + Dm * DFFm;

    round_all_kernel<<<1184, 256>>>(Wq, Wk, Wv, Wo, W1, W2, bq, bk, bv, wbuf, bqkv);

    cudaFuncSetAttribute(tf32gemm_kernel<false, false, false>, cudaFuncAttributeMaxDynamicSharedMemorySize, GEMM_SMEM);
    cudaFuncSetAttribute(tf32gemm_kernel<false, true,  false>, cudaFuncAttributeMaxDynamicSharedMemorySize, GEMM_SMEM);
    cudaFuncSetAttribute(tf32gemm_kernel<true,  false, true >, cudaFuncAttributeMaxDynamicSharedMemorySize, GEMM_SMEM);

    ln_kernel<<<NT, 256>>>(x, ln1_g, ln1_b, h);

    tf32gemm_kernel<false, false, false><<<dim3(DQKV / 128, NT / 128), 256, GEMM_SMEM>>>(h, rWqkv, bqkv, nullptr, qkv, NT, DQKV, Dm);

    const int ATTN_SMEM = 4 * 64 * ATS * 4 + 2 * 64 * 4;   // 74240 -> 3 CTA/SM
    cudaFuncSetAttribute(attn_tc_kernel, cudaFuncAttributeMaxDynamicSharedMemorySize, ATTN_SMEM);
    attn_tc_kernel<<<dim3(Ss / 64, Hh, Bb), 128, ATTN_SMEM>>>(qkv, am, ctx);

    dim3 gD(Dm / 128, NT / 128);
    tf32gemm_kernel<false, true, false><<<gD, 256, GEMM_SMEM>>>(ctx, rWo, bo, x, x1, NT, Dm, Dm);

    ln_kernel<<<NT, 256>>>(x1, ln2_g, ln2_b, h2);

    tf32gemm_kernel<true, false, true><<<dim3(DFFm / 128, NT / 128), 256, GEMM_SMEM>>>(h2, rW1, b1, nullptr, ff1, NT, DFFm, Dm);
    tf32gemm_kernel<false, true, false><<<gD, 256, GEMM_SMEM>>>(ff1, rW2, b2, x1, out, NT, Dm, DFFm);
}